// round 16
// baseline (speedup 1.0000x reference)
#include <cuda_runtime.h>
#include <cuda_fp16.h>
#include <mma.h>
#include <stdint.h>

using namespace nvcuda;

#define NN  50000
#define EE  800000
#define NBLK 196            // ceil(NN/256)
#define NPAD (NN + 128)     // row padding: wmma stores / unguarded A reads stay in-bounds

// W storage offsets (fp16 elements): layer0 128x128, layer1 128x128, layer2 128x64
#define WOFF0 0
#define WOFF1 16384
#define WOFF2 32768
#define WTOTAL 40960

// ---------------- scratch (device globals, zero-init at load) ---------------
__device__ __align__(16) __half g_th[NPAD * 128];   // t = h @ w_l, fp16 (gather operand)
__device__ __align__(16) float  g_r[NPAD * 128];    // r = h @ w_r, fp32
__device__ __align__(16) __half g_xh[NPAD * 128];   // fp16 of x
__device__ __align__(16) __half g_ah[NPAD * 128];   // fp16 of activations
__device__ __align__(16) __half g_wl[WTOTAL];       // Wl fp16, all layers
__device__ __align__(16) __half g_wr[WTOTAL];       // Wr fp16
__device__ int   g_degc[NN];
__device__ int   g_rowoff[NN + 1];
__device__ int   g_wptr[NN];
__device__ int   g_csr[EE];
__device__ float g_invdeg[NN];
__device__ int   g_bsum[NBLK];
__device__ int   g_bpre[NBLK];

// ---------------- cp.async helpers -------------------------------------------
__device__ __forceinline__ void cpa16(void* dst_smem, const void* src) {
    uint32_t d = (uint32_t)__cvta_generic_to_shared(dst_smem);
    asm volatile("cp.async.cg.shared.global [%0], [%1], 16;" :: "r"(d), "l"(src));
}
#define CP_COMMIT() asm volatile("cp.async.commit_group;" ::: "memory")
#define CP_WAIT1()  asm volatile("cp.async.wait_group 1;" ::: "memory")
#define CP_WAIT0()  asm volatile("cp.async.wait_group 0;" ::: "memory")

// ---------------- edge dtype probe --------------------------------------------
__device__ __forceinline__ int probe_is64(const void* ei) {
    int lane = threadIdx.x & 31;
    long long v = ((const long long*)ei)[lane];
    unsigned ok = __ballot_sync(0xffffffffu, v >= 0 && v < NN);
    return ok == 0xffffffffu;
}

__device__ __forceinline__ void load_edge(const void* ei, int e, int is64,
                                          int& s, int& d) {
    if (is64) {
        const long long* p = (const long long*)ei;
        s = (int)p[e];
        d = (int)p[EE + e];
    } else {
        const int* p = (const int*)ei;
        s = p[e];
        d = p[EE + e];
    }
    s = min(max(s, 0), NN - 1);
    d = min(max(d, 0), NN - 1);
}

// ---------------- one-time-per-launch conversions -----------------------------
__global__ void split_x_kernel(const float* __restrict__ x) {
    int i = blockIdx.x * blockDim.x + threadIdx.x;   // float4 index
    if (i >= NN * 32) return;
    float4 v = ((const float4*)x)[i];
    __half h[4];
    h[0] = __float2half_rn(v.x); h[1] = __float2half_rn(v.y);
    h[2] = __float2half_rn(v.z); h[3] = __float2half_rn(v.w);
    *(uint2*)(g_xh + (size_t)i * 4) = *(uint2*)h;
}

__global__ void split_w_kernel(const float* __restrict__ wl0, const float* __restrict__ wr0,
                               const float* __restrict__ wl1, const float* __restrict__ wr1,
                               const float* __restrict__ wl2, const float* __restrict__ wr2) {
    int idx = blockIdx.x * blockDim.x + threadIdx.x;
    if (idx >= WTOTAL) return;
    const float *wl, *wr;
    int local;
    if (idx < WOFF1)      { wl = wl0; wr = wr0; local = idx; }
    else if (idx < WOFF2) { wl = wl1; wr = wr1; local = idx - WOFF1; }
    else                  { wl = wl2; wr = wr2; local = idx - WOFF2; }
    g_wl[idx] = __float2half_rn(wl[local]);
    g_wr[idx] = __float2half_rn(wr[local]);
}

// ---------------- graph preprocessing -----------------------------------------
__global__ void count_deg_kernel(const void* __restrict__ ei) {
    int is64 = probe_is64(ei);
    int e = blockIdx.x * blockDim.x + threadIdx.x;
    if (e < EE) {
        int s, d;
        load_edge(ei, e, is64, s, d);
        atomicAdd(&g_degc[d], 1);
    }
}

__global__ void blocksum_kernel() {
    int i = blockIdx.x * 256 + threadIdx.x;
    int v = (i < NN) ? g_degc[i] : 0;
#pragma unroll
    for (int off = 16; off > 0; off >>= 1)
        v += __shfl_down_sync(0xffffffffu, v, off);
    __shared__ int ws[8];
    if ((threadIdx.x & 31) == 0) ws[threadIdx.x >> 5] = v;
    __syncthreads();
    if (threadIdx.x == 0) {
        int s = 0;
#pragma unroll
        for (int w = 0; w < 8; w++) s += ws[w];
        g_bsum[blockIdx.x] = s;
    }
}

__global__ void scan_bsum_kernel() {
    __shared__ int sh[256];
    int t = threadIdx.x;
    int v = (t < NBLK) ? g_bsum[t] : 0;
    sh[t] = v;
    __syncthreads();
#pragma unroll
    for (int off = 1; off < 256; off <<= 1) {
        int u = (t >= off) ? sh[t - off] : 0;
        __syncthreads();
        sh[t] += u;
        __syncthreads();
    }
    if (t < NBLK) g_bpre[t] = sh[t] - v;
    if (t == NBLK - 1) g_rowoff[NN] = sh[t];
}

__global__ void write_off_kernel() {
    __shared__ int sh[256];
    int t = threadIdx.x;
    int i = blockIdx.x * 256 + t;
    int v = (i < NN) ? g_degc[i] : 0;
    sh[t] = v;
    __syncthreads();
#pragma unroll
    for (int off = 1; off < 256; off <<= 1) {
        int u = (t >= off) ? sh[t - off] : 0;
        __syncthreads();
        sh[t] += u;
        __syncthreads();
    }
    if (i < NN) {
        int excl = g_bpre[blockIdx.x] + sh[t] - v;
        g_rowoff[i] = excl;
        g_wptr[i]   = excl;
        g_invdeg[i] = 1.0f / fmaxf((float)v, 1.0f);
        g_degc[i]   = 0;
    }
}

__global__ void fill_csr_kernel(const void* __restrict__ ei) {
    int is64 = probe_is64(ei);
    int e = blockIdx.x * blockDim.x + threadIdx.x;
    if (e < EE) {
        int s, d;
        load_edge(ei, e, is64, s, d);
        int p = atomicAdd(&g_wptr[d], 1);
        if (p >= 0 && p < EE) g_csr[p] = s;
    }
}

// ---------------- fused dual wmma GEMM with cp.async pipeline ----------------
// t(fp16) = A@Wl, r(fp32) = A@Wr.  Pure fp16 operands, fp32 accumulators.
// Double-buffered staging: chunk c+1 prefetched via cp.async.cg while tensor
// cores process chunk c -> global latency hidden, staging registers freed.
// CTA: 64 rows x (Wl||Wr), 256 threads, 8 warps 2m x 4n; 2 CTAs/SM pinned.
#define KCH 32
#define KP  40     // A smem row stride (fp16 elems)

template <int COLT>   // 128 or 64; fused width = 2*COLT
__global__ __launch_bounds__(256, 2)
void gemm_wmma_kernel(int useX, int wOff) {
    constexpr int WTOT = 2 * COLT;      // 256 or 128
    constexpr int CP = WTOT + 8;        // W smem stride
    constexpr int WN = WTOT / 4;        // cols per warp (64 or 32)
    constexpr int NF = WN / 16;         // 16-col frags per warp (4 or 2)
    constexpr int NCH = 128 / KCH;      // 4 chunks

    __shared__ __align__(16) __half Ah[2][64 * KP];    // 2 x 5.1 KB
    __shared__ __align__(16) __half Ws[2][KCH * CP];   // 2 x 16.9 / 8.7 KB
    // epilogue bounce (4 t-warps x 32 x WN fp32 = 32/16 KB) reuses Ah+Ws
    static_assert(4 * 32 * WN * 4 <= (int)sizeof(Ah) + (int)sizeof(Ws), "bounce fits");

    const __half* ah = useX ? g_xh : g_ah;
    const __half* wl = g_wl + wOff;
    const __half* wr = g_wr + wOff;

    const int tid = threadIdx.x;
    const int wid = tid >> 5;
    const int lane = tid & 31;
    const int wm = wid & 1;           // m-tile 0..1 (32 rows each)
    const int wn = wid >> 1;          // n-tile 0..3 (WN cols each)
    const int rowBase = blockIdx.x * 64;

    const int arow = tid >> 2;            // 0..63
    const int akq  = (tid & 3) * 8;       // k offset 0,8,16,24 (16B = 8 fp16)

    // stage chunk c into buffer b (cp.async, no registers)
    auto load_chunk = [&](int c, int b) {
        size_t gsrc = (size_t)(rowBase + arow) * 128 + c * KCH + akq;
        cpa16(&Ah[b][arow * KP + akq], ah + gsrc);
#pragma unroll
        for (int f = tid; f < KCH * (WTOT / 8); f += 256) {
            int k = f / (WTOT / 8);
            int n = (f % (WTOT / 8)) * 8;
            const __half* src = (n < COLT) ? (wl + (size_t)(c * KCH + k) * COLT + n)
                                           : (wr + (size_t)(c * KCH + k) * COLT + (n - COLT));
            cpa16(&Ws[b][k * CP + n], src);
        }
    };

    wmma::fragment<wmma::accumulator, 16, 16, 16, float> acc[2][NF];
#pragma unroll
    for (int m = 0; m < 2; m++)
#pragma unroll
        for (int f = 0; f < NF; f++) wmma::fill_fragment(acc[m][f], 0.0f);

    load_chunk(0, 0);
    CP_COMMIT();

#pragma unroll
    for (int c = 0; c < NCH; c++) {
        int b = c & 1;
        if (c + 1 < NCH) {
            load_chunk(c + 1, (c + 1) & 1);
            CP_COMMIT();
            CP_WAIT1();     // chunk c resident, c+1 may be in flight
        } else {
            CP_WAIT0();
        }
        __syncthreads();

#pragma unroll
        for (int kk = 0; kk < KCH; kk += 16) {
            wmma::fragment<wmma::matrix_a, 16, 16, 16, __half,
                           wmma::row_major> a0, a1;
            wmma::load_matrix_sync(a0, &Ah[b][(wm * 32) * KP + kk], KP);
            wmma::load_matrix_sync(a1, &Ah[b][(wm * 32 + 16) * KP + kk], KP);
#pragma unroll
            for (int f = 0; f < NF; f++) {
                wmma::fragment<wmma::matrix_b, 16, 16, 16, __half,
                               wmma::row_major> bfr;
                int ncol = wn * WN + f * 16;
                wmma::load_matrix_sync(bfr, &Ws[b][kk * CP + ncol], CP);
                wmma::mma_sync(acc[0][f], a0, bfr, acc[0][f]);
                wmma::mma_sync(acc[1][f], a1, bfr, acc[1][f]);
            }
        }
        __syncthreads();   // protect buffer b before chunk c+2 overwrites it
    }

    if (wn < 2) {
        // ---- t half: bounce fp32 frags through smem, emit fp16 ----
        float* bw = (float*)&Ah[0][0] + (size_t)wid * 32 * WN;   // warp-private
#pragma unroll
        for (int m = 0; m < 2; m++)
#pragma unroll
            for (int f = 0; f < NF; f++)
                wmma::store_matrix_sync(bw + m * 16 * WN + f * 16, acc[m][f],
                                        WN, wmma::mem_row_major);
        __syncwarp();
        constexpr int VPR = WN / 4;   // float4 vectors per row (16 or 8)
#pragma unroll
        for (int i = 0; i < VPR; i++) {
            int v = lane + 32 * i;
            int row = v / VPR;
            int col = (v % VPR) * 4;
            float4 fv = *(float4*)(bw + row * WN + col);
            __half h4[4] = {__float2half_rn(fv.x), __float2half_rn(fv.y),
                            __float2half_rn(fv.z), __float2half_rn(fv.w)};
            int rg = rowBase + wm * 32 + row;
            *(uint2*)(g_th + (size_t)rg * COLT + wn * WN + col) = *(uint2*)h4;
        }
    } else {
        // ---- r half: direct fp32 wmma store ----
#pragma unroll
        for (int m = 0; m < 2; m++) {
            int r = rowBase + wm * 32 + m * 16;
#pragma unroll
            for (int f = 0; f < NF; f++) {
                int ncol = wn * WN + f * 16 - COLT;
                wmma::store_matrix_sync(g_r + (size_t)r * COLT + ncol, acc[m][f],
                                        COLT, wmma::mem_row_major);
            }
        }
    }
}

// ---------------- aggregation + combine --------------------------------------
// Gathers fp16 t rows, accumulates fp32.
// D==128 (hidden): writes fp16 activations to g_ah. D==64 (final): fp32 outp.
template <int D, bool RELU>
__global__ __launch_bounds__(256)
void combine_kernel(const float* __restrict__ bias, float* __restrict__ outp) {
    int gw = (blockIdx.x * blockDim.x + threadIdx.x) >> 5;
    int lane = threadIdx.x & 31;
    if (gw >= NN) return;

    int beg = g_rowoff[gw];
    int end = g_rowoff[gw + 1];
    const __half* t = g_th;

    if (D == 128) {
        float a0 = 0.f, a1 = 0.f, a2 = 0.f, a3 = 0.f;
        int j = beg;
        for (; j + 4 <= end; j += 4) {
            int s0 = g_csr[j], s1 = g_csr[j + 1], s2 = g_csr[j + 2], s3 = g_csr[j + 3];
            uint2 r0 = *(const uint2*)(t + (size_t)s0 * 128 + lane * 4);
            uint2 r1 = *(const uint2*)(t + (size_t)s1 * 128 + lane * 4);
            uint2 r2 = *(const uint2*)(t + (size_t)s2 * 128 + lane * 4);
            uint2 r3 = *(const uint2*)(t + (size_t)s3 * 128 + lane * 4);
#pragma unroll
            for (int q = 0; q < 4; q++) {
                uint2 rr = (q == 0) ? r0 : (q == 1) ? r1 : (q == 2) ? r2 : r3;
                float2 f0 = __half22float2(*(__half2*)&rr.x);
                float2 f1 = __half22float2(*(__half2*)&rr.y);
                a0 += f0.x; a1 += f0.y; a2 += f1.x; a3 += f1.y;
            }
        }
        for (; j < end; j++) {
            int s = g_csr[j];
            uint2 rr = *(const uint2*)(t + (size_t)s * 128 + lane * 4);
            float2 f0 = __half22float2(*(__half2*)&rr.x);
            float2 f1 = __half22float2(*(__half2*)&rr.y);
            a0 += f0.x; a1 += f0.y; a2 += f1.x; a3 += f1.y;
        }
        float inv = g_invdeg[gw];
        float4 rr = *(const float4*)(g_r + (size_t)gw * 128 + lane * 4);
        float o[4];
        o[0] = a0 * inv + bias[lane * 4 + 0] + rr.x;
        o[1] = a1 * inv + bias[lane * 4 + 1] + rr.y;
        o[2] = a2 * inv + bias[lane * 4 + 2] + rr.z;
        o[3] = a3 * inv + bias[lane * 4 + 3] + rr.w;
        __half h[4];
#pragma unroll
        for (int e = 0; e < 4; e++) {
            float v = RELU ? fmaxf(o[e], 0.f) : o[e];
            h[e] = __float2half_rn(v);
        }
        *(uint2*)(g_ah + (size_t)gw * 128 + lane * 4) = *(uint2*)h;
    } else {
        float a0 = 0.f, a1 = 0.f;
        int j = beg;
        for (; j + 4 <= end; j += 4) {
            int s0 = g_csr[j], s1 = g_csr[j + 1], s2 = g_csr[j + 2], s3 = g_csr[j + 3];
            unsigned r0 = *(const unsigned*)(t + (size_t)s0 * 64 + lane * 2);
            unsigned r1 = *(const unsigned*)(t + (size_t)s1 * 64 + lane * 2);
            unsigned r2 = *(const unsigned*)(t + (size_t)s2 * 64 + lane * 2);
            unsigned r3 = *(const unsigned*)(t + (size_t)s3 * 64 + lane * 2);
#pragma unroll
            for (int q = 0; q < 4; q++) {
                unsigned rr = (q == 0) ? r0 : (q == 1) ? r1 : (q == 2) ? r2 : r3;
                float2 f = __half22float2(*(__half2*)&rr);
                a0 += f.x; a1 += f.y;
            }
        }
        for (; j < end; j++) {
            int s = g_csr[j];
            unsigned rr = *(const unsigned*)(t + (size_t)s * 64 + lane * 2);
            float2 f = __half22float2(*(__half2*)&rr);
            a0 += f.x; a1 += f.y;
        }
        float inv = g_invdeg[gw];
        float2 rr = *(const float2*)(g_r + (size_t)gw * 64 + lane * 2);
        float2 o;
        o.x = a0 * inv + bias[lane * 2 + 0] + rr.x;
        o.y = a1 * inv + bias[lane * 2 + 1] + rr.y;
        if (RELU) { o.x = fmaxf(o.x, 0.f); o.y = fmaxf(o.y, 0.f); }
        *(float2*)(outp + (size_t)gw * 64 + lane * 2) = o;
    }
}

// ---------------- launch --------------------------------------------------------
extern "C" void kernel_launch(void* const* d_in, const int* in_sizes, int n_in,
                              void* d_out, int out_size) {
    const float* x    = (const float*)d_in[0];
    const void*  ei   = d_in[1];
    const float* w_l0 = (const float*)d_in[2];
    const float* b0   = (const float*)d_in[3];
    const float* w_r0 = (const float*)d_in[4];
    const float* w_l1 = (const float*)d_in[5];
    const float* b1   = (const float*)d_in[6];
    const float* w_r1 = (const float*)d_in[7];
    const float* w_l2 = (const float*)d_in[8];
    const float* b2   = (const float*)d_in[9];
    const float* w_r2 = (const float*)d_in[10];
    float* outp = (float*)d_out;

    const int gemmBlocks = (NN + 63) / 64;        // 782
    const int combBlocks = (NN * 32 + 255) / 256; // 6250

    split_x_kernel<<<(NN * 32 + 255) / 256, 256>>>(x);
    split_w_kernel<<<(WTOTAL + 255) / 256, 256>>>(w_l0, w_r0, w_l1, w_r1, w_l2, w_r2);
    count_deg_kernel<<<(EE + 255) / 256, 256>>>(ei);
    gemm_wmma_kernel<128><<<gemmBlocks, 256>>>(1, WOFF0);     // ncu slot
    blocksum_kernel<<<NBLK, 256>>>();
    scan_bsum_kernel<<<1, 256>>>();
    write_off_kernel<<<NBLK, 256>>>();
    fill_csr_kernel<<<(EE + 255) / 256, 256>>>(ei);
    combine_kernel<128, true><<<combBlocks, 256>>>(b0, nullptr);
    gemm_wmma_kernel<128><<<gemmBlocks, 256>>>(0, WOFF1);
    combine_kernel<128, true><<<combBlocks, 256>>>(b1, nullptr);
    gemm_wmma_kernel<64><<<gemmBlocks, 256>>>(0, WOFF2);
    combine_kernel<64, false><<<combBlocks, 256>>>(b2, outp);
}